// round 7
// baseline (speedup 1.0000x reference)
#include <cuda_runtime.h>
#include <cstdint>
#include <cstddef>

// Problem constants (fixed by the benchmark shapes)
#define N_QUERY 32768   // 1024 rays * 32 samples
#define N_LIDAR 8192
#define FDIM    128
#define THREADS 384
#define QPB     256     // queries per block
#define SPLIT   3       // lidar thirds per block (tile-granular, uneven)
#define NBLK    (N_QUERY / QPB)     // 128 blocks
#define TILE    64      // points per guarded best-update

using u64 = unsigned long long;

// Tile-granular third boundaries: 128 tiles split 43/43/42.
__device__ __constant__ int kThirdBeg[4] = {0, 43 * TILE, 86 * TILE, 128 * TILE};

// ---- packed f32x2 helpers (sm_103a): bitwise-identical to scalar rn ops ----
__device__ __forceinline__ u64 dup2(float x) {
    u64 r; asm("mov.b64 %0, {%1, %1};" : "=l"(r) : "f"(x)); return r;
}
__device__ __forceinline__ u64 mul2(u64 a, u64 b) {
    u64 d; asm("mul.rn.f32x2 %0, %1, %2;" : "=l"(d) : "l"(a), "l"(b)); return d;
}
__device__ __forceinline__ u64 fma2(u64 a, u64 b, u64 c) {
    u64 d; asm("fma.rn.f32x2 %0, %1, %2, %3;" : "=l"(d) : "l"(a), "l"(b), "l"(c)); return d;
}
__device__ __forceinline__ u64 add2(u64 a, u64 b) {
    u64 d; asm("add.rn.f32x2 %0, %1, %2;" : "=l"(d) : "l"(a), "l"(b)); return d;
}
__device__ __forceinline__ float2 asf2(u64 v) {
    float2 f; asm("mov.b64 {%0, %1}, %2;" : "=f"(f.x), "=f"(f.y) : "l"(v)); return f;
}
__device__ __forceinline__ float min8(u64 a, u64 b, u64 c, u64 d) {
    float2 f0 = asf2(a), f1 = asf2(b), f2 = asf2(c), f3 = asf2(d);
    return fminf(fminf(fminf(f0.x, f0.y), fminf(f1.x, f1.y)),
                 fminf(fminf(f2.x, f2.y), fminf(f3.x, f3.y)));
}

// Exact first-index recovery in a 64-point tile (bit-identical scalar math).
__device__ __forceinline__ int recover_idx(
    const float* __restrict__ skx, const float* __restrict__ sky,
    const float* __restrict__ skz, const float* __restrict__ sks,
    int btile, float qx, float qy, float qz, float qs, float best)
{
    int bi = btile;
    bool found = false;
    #pragma unroll 4
    for (int i = 0; i < TILE; i++) {
        const int j = btile + i;
        float cross = __fmaf_rn(qz, skz[j],
                      __fmaf_rn(qy, sky[j], __fmul_rn(qx, skx[j])));
        float d2 = __fadd_rn(__fmaf_rn(cross, -2.0f, qs), sks[j]);
        if (!found && d2 == best) { bi = j; found = true; }
    }
    return bi;
}

__global__ void __launch_bounds__(THREADS, 1)
nn_gather_kernel(const float* __restrict__ pts,
                 const float* __restrict__ lidar,
                 const float* __restrict__ features,
                 float* __restrict__ out)
{
    extern __shared__ float sm[];
    float* skx = sm;
    float* sky = sm + N_LIDAR;
    float* skz = sm + 2 * N_LIDAR;
    float* sks = sm + 3 * N_LIDAR;
    float* cd2  = sm + 4 * N_LIDAR;                        // [SPLIT][QPB]
    int*   cidx = (int*)(sm + 4 * N_LIDAR + SPLIT * QPB);  // [SPLIT][QPB]
    int*   sidx = (int*)(sm + 4 * N_LIDAR + 2 * SPLIT * QPB); // [QPB]

    const int tid = threadIdx.x;

    // Cooperative SoA fill of lidar points + ||k||^2 (stepwise rounding (x^2+y^2)+z^2)
    for (int i = tid; i < N_LIDAR; i += THREADS) {
        float kx = lidar[3 * i + 0];
        float ky = lidar[3 * i + 1];
        float kz = lidar[3 * i + 2];
        skx[i] = kx; sky[i] = ky; skz[i] = kz;
        sks[i] = __fadd_rn(__fadd_rn(__fmul_rn(kx, kx), __fmul_rn(ky, ky)),
                           __fmul_rn(kz, kz));
    }
    __syncthreads();

    // Thread task: query pair (tid & 127) over lidar third (tid >> 7).
    // All 32 lanes of a warp share the same third -> all inner LDS are broadcasts.
    const int pair  = tid & 127;
    const int third = tid >> 7;            // 0, 1, 2
    const int q0 = 2 * pair;               // block-local query ids q0, q0+1
    const int m0 = blockIdx.x * QPB + q0;

    const float qx0 = pts[3 * m0 + 0], qy0 = pts[3 * m0 + 1], qz0 = pts[3 * m0 + 2];
    const float qx1 = pts[3 * m0 + 3], qy1 = pts[3 * m0 + 4], qz1 = pts[3 * m0 + 5];
    const float qs0 = __fadd_rn(__fadd_rn(__fmul_rn(qx0, qx0), __fmul_rn(qy0, qy0)),
                                __fmul_rn(qz0, qz0));
    const float qs1 = __fadd_rn(__fadd_rn(__fmul_rn(qx1, qx1), __fmul_rn(qy1, qy1)),
                                __fmul_rn(qz1, qz1));

    const u64 QX0 = dup2(qx0), QY0 = dup2(qy0), QZ0 = dup2(qz0), QS0 = dup2(qs0);
    const u64 QX1 = dup2(qx1), QY1 = dup2(qy1), QZ1 = dup2(qz1), QS1 = dup2(qs1);
    const u64 NEG2 = dup2(-2.0f);

    const int tbeg = kThirdBeg[third];
    const int tend = kThirdBeg[third + 1];

    float best0 = __int_as_float(0x7f800000), best1 = best0;
    int btile0 = tbeg, btile1 = tbeg;

    for (int t = tbeg; t < tend; t += TILE) {
        float tm0 = __int_as_float(0x7f800000);
        float tm1 = tm0;

        #pragma unroll
        for (int g = 0; g < TILE / 8; g++) {
            const int j = t + 8 * g;

            // cross = fma(qz,kz, fma(qy,ky, rn(qx*kx)))  — reference dot order
            ulonglong2 ka = *(const ulonglong2*)(skx + j);
            ulonglong2 kb = *(const ulonglong2*)(skx + j + 4);
            u64 a0 = mul2(QX0, ka.x), a1 = mul2(QX0, ka.y);
            u64 a2 = mul2(QX0, kb.x), a3 = mul2(QX0, kb.y);
            u64 b0 = mul2(QX1, ka.x), b1 = mul2(QX1, ka.y);
            u64 b2 = mul2(QX1, kb.x), b3 = mul2(QX1, kb.y);

            ka = *(const ulonglong2*)(sky + j);
            kb = *(const ulonglong2*)(sky + j + 4);
            a0 = fma2(QY0, ka.x, a0); a1 = fma2(QY0, ka.y, a1);
            a2 = fma2(QY0, kb.x, a2); a3 = fma2(QY0, kb.y, a3);
            b0 = fma2(QY1, ka.x, b0); b1 = fma2(QY1, ka.y, b1);
            b2 = fma2(QY1, kb.x, b2); b3 = fma2(QY1, kb.y, b3);

            ka = *(const ulonglong2*)(skz + j);
            kb = *(const ulonglong2*)(skz + j + 4);
            a0 = fma2(QZ0, ka.x, a0); a1 = fma2(QZ0, ka.y, a1);
            a2 = fma2(QZ0, kb.x, a2); a3 = fma2(QZ0, kb.y, a3);
            b0 = fma2(QZ1, ka.x, b0); b1 = fma2(QZ1, ka.y, b1);
            b2 = fma2(QZ1, kb.x, b2); b3 = fma2(QZ1, kb.y, b3);

            // d2 = rn( rn(qs - 2*cross) + ks )
            ka = *(const ulonglong2*)(sks + j);
            kb = *(const ulonglong2*)(sks + j + 4);
            a0 = add2(fma2(a0, NEG2, QS0), ka.x);
            a1 = add2(fma2(a1, NEG2, QS0), ka.y);
            a2 = add2(fma2(a2, NEG2, QS0), kb.x);
            a3 = add2(fma2(a3, NEG2, QS0), kb.y);
            b0 = add2(fma2(b0, NEG2, QS1), ka.x);
            b1 = add2(fma2(b1, NEG2, QS1), ka.y);
            b2 = add2(fma2(b2, NEG2, QS1), kb.x);
            b3 = add2(fma2(b3, NEG2, QS1), kb.y);

            tm0 = fminf(tm0, min8(a0, a1, a2, a3));
            tm1 = fminf(tm1, min8(b0, b1, b2, b3));
        }

        if (tm0 < best0) { best0 = tm0; btile0 = t; }  // strict < : earliest tile on ties
        if (tm1 < best1) { best1 = tm1; btile1 = t; }
    }

    // Exact first-index recovery within winning tiles (global lidar indices).
    const int bi0 = recover_idx(skx, sky, skz, sks, btile0, qx0, qy0, qz0, qs0, best0);
    const int bi1 = recover_idx(skx, sky, skz, sks, btile1, qx1, qy1, qz1, qs1, best1);

    cd2[third * QPB + q0]     = best0;  cidx[third * QPB + q0]     = bi0;
    cd2[third * QPB + q0 + 1] = best1;  cidx[third * QPB + q0 + 1] = bi1;
    __syncthreads();

    // Combine the 3 third-candidates per query (ascending third, strict <).
    if (tid < QPB) {
        float b = cd2[tid];
        int   i = cidx[tid];
        #pragma unroll
        for (int s = 1; s < SPLIT; s++) {
            float d = cd2[s * QPB + tid];
            int   j = cidx[s * QPB + tid];
            if (d < b) { b = d; i = j; }  // earlier third kept on ties (lower index)
        }
        sidx[tid] = i;
    }
    __syncthreads();

    // Warp-cooperative coalesced gather: one query row == 32 lanes x float4
    const int lane = tid & 31;
    const int warp = tid >> 5;
    const size_t qbase = (size_t)blockIdx.x * QPB;
    for (int qq = warp; qq < QPB; qq += THREADS / 32) {
        const int src = sidx[qq];
        const float4 v = *(const float4*)(features + (size_t)src * FDIM + lane * 4);
        *(float4*)(out + (qbase + qq) * FDIM + lane * 4) = v;
    }
}

extern "C" void kernel_launch(void* const* d_in, const int* in_sizes, int n_in,
                              void* d_out, int out_size) {
    const float* pts      = (const float*)d_in[0];  // (1, 1024, 32, 3)
    const float* lidar    = (const float*)d_in[1];  // (1, 8192, 3)
    const float* features = (const float*)d_in[2];  // (1, 8192, 128)
    float* out = (float*)d_out;                     // (1, 1024, 32, 128)

    // 128 KB lidar SoA + combine scratch
    const int smem_bytes = (4 * N_LIDAR + 2 * SPLIT * QPB + QPB) * (int)sizeof(float);
    cudaFuncSetAttribute(nn_gather_kernel,
                         cudaFuncAttributeMaxDynamicSharedMemorySize, smem_bytes);

    nn_gather_kernel<<<NBLK, THREADS, smem_bytes>>>(pts, lidar, features, out);
}

// round 8
// speedup vs baseline: 1.6529x; 1.6529x over previous
#include <cuda_runtime.h>
#include <cstdint>
#include <cstddef>

// Problem constants (fixed by the benchmark shapes)
#define N_QUERY 32768   // 1024 rays * 32 samples
#define N_LIDAR 8192
#define FDIM    128
#define THREADS 256
#define WARPS   (THREADS / 32)      // 8
#define QPW     16                  // queries per warp-pass (8 packed pairs)
#define PASSES  2                   // 8 warps * 2 passes * 16 = 256 queries/block
#define QPB     256
#define NBLK    (N_QUERY / QPB)     // 128 blocks
#define NITER   (N_LIDAR / 32)      // 256 iterations (one point per lane)
#define TI      8                   // iterations per tile (256 points/tile)
#define NTILE   (NITER / TI)        // 32 tiles

using u64 = unsigned long long;

// ---- packed f32x2 helpers (sm_103a): bitwise-identical per-half to scalar rn ----
__device__ __forceinline__ u64 pack2(float lo, float hi) {
    u64 r; asm("mov.b64 %0, {%1, %2};" : "=l"(r) : "f"(lo), "f"(hi)); return r;
}
__device__ __forceinline__ u64 dup2(float x) {
    u64 r; asm("mov.b64 %0, {%1, %1};" : "=l"(r) : "f"(x)); return r;
}
__device__ __forceinline__ u64 mul2(u64 a, u64 b) {
    u64 d; asm("mul.rn.f32x2 %0, %1, %2;" : "=l"(d) : "l"(a), "l"(b)); return d;
}
__device__ __forceinline__ u64 fma2(u64 a, u64 b, u64 c) {
    u64 d; asm("fma.rn.f32x2 %0, %1, %2, %3;" : "=l"(d) : "l"(a), "l"(b), "l"(c)); return d;
}
__device__ __forceinline__ u64 add2(u64 a, u64 b) {
    u64 d; asm("add.rn.f32x2 %0, %1, %2;" : "=l"(d) : "l"(a), "l"(b)); return d;
}
__device__ __forceinline__ float2 asf2(u64 v) {
    float2 f; asm("mov.b64 {%0, %1}, %2;" : "=f"(f.x), "=f"(f.y) : "l"(v)); return f;
}

__global__ void __launch_bounds__(THREADS, 1)
nn_gather_kernel(const float* __restrict__ pts,
                 const float* __restrict__ lidar,
                 const float* __restrict__ features,
                 float* __restrict__ out)
{
    extern __shared__ float4 sk4[];                 // [N_LIDAR] (x, y, z, ||k||^2)
    __shared__ int sidx[QPB];

    const int tid  = threadIdx.x;
    const int lane = tid & 31;
    const int warp = tid >> 5;

    // Cooperative AoS fill: point + ||k||^2 with stepwise rounding (x^2+y^2)+z^2
    for (int i = tid; i < N_LIDAR; i += THREADS) {
        float kx = lidar[3 * i + 0];
        float ky = lidar[3 * i + 1];
        float kz = lidar[3 * i + 2];
        float ks = __fadd_rn(__fadd_rn(__fmul_rn(kx, kx), __fmul_rn(ky, ky)),
                             __fmul_rn(kz, kz));
        sk4[i] = make_float4(kx, ky, kz, ks);
    }
    __syncthreads();

    const float INF = __int_as_float(0x7f800000);

    for (int pass = 0; pass < PASSES; pass++) {
        // This warp-pass owns 16 consecutive queries.
        const int ql0 = (pass * WARPS + warp) * QPW;        // block-local query base
        const int mg0 = blockIdx.x * QPB + ql0;             // global query base

        // Load queries (uniform across lanes), exact stepwise ||q||^2.
        float qx[QPW], qy[QPW], qz[QPW], qs[QPW];
        #pragma unroll
        for (int q = 0; q < QPW; q++) {
            qx[q] = __ldg(pts + 3 * (mg0 + q) + 0);
            qy[q] = __ldg(pts + 3 * (mg0 + q) + 1);
            qz[q] = __ldg(pts + 3 * (mg0 + q) + 2);
            qs[q] = __fadd_rn(__fadd_rn(__fmul_rn(qx[q], qx[q]),
                                        __fmul_rn(qy[q], qy[q])),
                              __fmul_rn(qz[q], qz[q]));
        }
        // Pack query pairs (2q, 2q+1) per component.
        u64 PQX[QPW / 2], PQY[QPW / 2], PQZ[QPW / 2], PQS[QPW / 2];
        #pragma unroll
        for (int p = 0; p < QPW / 2; p++) {
            PQX[p] = pack2(qx[2 * p], qx[2 * p + 1]);
            PQY[p] = pack2(qy[2 * p], qy[2 * p + 1]);
            PQZ[p] = pack2(qz[2 * p], qz[2 * p + 1]);
            PQS[p] = pack2(qs[2 * p], qs[2 * p + 1]);
        }
        const u64 NEG2 = dup2(-2.0f);

        float best[QPW];
        int   btile[QPW];
        #pragma unroll
        for (int q = 0; q < QPW; q++) { best[q] = INF; btile[q] = 0; }

        // Main scan: lane handles points i*32+lane. Tile = TI iters = 256 points.
        for (int t = 0; t < NTILE; t++) {
            float tmin[QPW];
            #pragma unroll
            for (int q = 0; q < QPW; q++) tmin[q] = INF;

            #pragma unroll 2
            for (int ii = 0; ii < TI; ii++) {
                const int i = t * TI + ii;
                const float4 k = sk4[i * 32 + lane];        // coalesced LDS.128
                const u64 KX = dup2(k.x), KY = dup2(k.y);
                const u64 KZ = dup2(k.z), KS = dup2(k.w);

                #pragma unroll
                for (int p = 0; p < QPW / 2; p++) {
                    // cross = fma(qz,kz, fma(qy,ky, rn(qx*kx)))  — reference order
                    u64 cross = fma2(PQZ[p], KZ, fma2(PQY[p], KY, mul2(PQX[p], KX)));
                    // d2 = rn( rn(qs - 2*cross) + ks )
                    u64 d2 = add2(fma2(cross, NEG2, PQS[p]), KS);
                    float2 f = asf2(d2);
                    tmin[2 * p]     = fminf(tmin[2 * p],     f.x);
                    tmin[2 * p + 1] = fminf(tmin[2 * p + 1], f.y);
                }
            }

            #pragma unroll
            for (int q = 0; q < QPW; q++) {
                // strict < : keeps the FIRST tile where this lane's min appeared
                if (tmin[q] < best[q]) { best[q] = tmin[q]; btile[q] = t; }
            }
        }

        // Epilogue: per query -> warp min value, earliest tile, exact first index.
        for (int q = 0; q < QPW; q++) {
            float v = best[q];
            #pragma unroll
            for (int off = 16; off > 0; off >>= 1)
                v = fminf(v, __shfl_xor_sync(0xffffffffu, v, off));

            int tl = (best[q] == v) ? btile[q] : 0x7fffffff;
            #pragma unroll
            for (int off = 16; off > 0; off >>= 1)
                tl = min(tl, __shfl_xor_sync(0xffffffffu, tl, off));

            // Rescan winning tile scalar-exactly (bit-identical rounding).
            int cand = 0x7fffffff;
            const float fqx = qx[q], fqy = qy[q], fqz = qz[q], fqs = qs[q];
            #pragma unroll
            for (int ii = 0; ii < TI; ii++) {
                const int j = tl * (TI * 32) + ii * 32 + lane;
                const float4 k = sk4[j];
                float cross = __fmaf_rn(fqz, k.z,
                              __fmaf_rn(fqy, k.y, __fmul_rn(fqx, k.x)));
                float d2 = __fadd_rn(__fmaf_rn(cross, -2.0f, fqs), k.w);
                if (d2 == v && j < cand) cand = j;
            }
            #pragma unroll
            for (int off = 16; off > 0; off >>= 1)
                cand = min(cand, __shfl_xor_sync(0xffffffffu, cand, off));

            if (lane == 0) sidx[ql0 + q] = cand;
        }
    }
    __syncthreads();

    // Warp-cooperative coalesced gather: one query row == 32 lanes x float4
    const size_t qbase = (size_t)blockIdx.x * QPB;
    for (int qq = warp; qq < QPB; qq += WARPS) {
        const int src = sidx[qq];
        const float4 v = *(const float4*)(features + (size_t)src * FDIM + lane * 4);
        *(float4*)(out + (qbase + qq) * FDIM + lane * 4) = v;
    }
}

extern "C" void kernel_launch(void* const* d_in, const int* in_sizes, int n_in,
                              void* d_out, int out_size) {
    const float* pts      = (const float*)d_in[0];  // (1, 1024, 32, 3)
    const float* lidar    = (const float*)d_in[1];  // (1, 8192, 3)
    const float* features = (const float*)d_in[2];  // (1, 8192, 128)
    float* out = (float*)d_out;                     // (1, 1024, 32, 128)

    const int smem_bytes = N_LIDAR * (int)sizeof(float4);   // 128 KB AoS
    cudaFuncSetAttribute(nn_gather_kernel,
                         cudaFuncAttributeMaxDynamicSharedMemorySize, smem_bytes);

    nn_gather_kernel<<<NBLK, THREADS, smem_bytes>>>(pts, lidar, features, out);
}

// round 9
// speedup vs baseline: 1.8578x; 1.1240x over previous
#include <cuda_runtime.h>
#include <cstdint>
#include <cstddef>

// Problem constants (fixed by the benchmark shapes)
#define N_QUERY 32768   // 1024 rays * 32 samples
#define N_LIDAR 8192
#define FDIM    128
#define THREADS 512
#define WARPS   (THREADS / 32)      // 16
#define QPW     8                   // queries per warp-pass (4 packed pairs)
#define PASSES  2                   // 16 warps * 2 passes * 8 = 256 queries/block
#define QPB     256
#define NBLK    (N_QUERY / QPB)     // 128 blocks
#define NITER   (N_LIDAR / 32)      // 256 iterations (one point per lane)
#define TI      8                   // iterations per tile (256 points/tile)
#define NTILE   (NITER / TI)        // 32 tiles

using u64 = unsigned long long;

// ---- packed f32x2 helpers (sm_103a): bitwise-identical per-half to scalar rn ----
__device__ __forceinline__ u64 pack2(float lo, float hi) {
    u64 r; asm("mov.b64 %0, {%1, %2};" : "=l"(r) : "f"(lo), "f"(hi)); return r;
}
__device__ __forceinline__ u64 dup2(float x) {
    u64 r; asm("mov.b64 %0, {%1, %1};" : "=l"(r) : "f"(x)); return r;
}
__device__ __forceinline__ u64 mul2(u64 a, u64 b) {
    u64 d; asm("mul.rn.f32x2 %0, %1, %2;" : "=l"(d) : "l"(a), "l"(b)); return d;
}
__device__ __forceinline__ u64 fma2(u64 a, u64 b, u64 c) {
    u64 d; asm("fma.rn.f32x2 %0, %1, %2, %3;" : "=l"(d) : "l"(a), "l"(b), "l"(c)); return d;
}
__device__ __forceinline__ u64 add2(u64 a, u64 b) {
    u64 d; asm("add.rn.f32x2 %0, %1, %2;" : "=l"(d) : "l"(a), "l"(b)); return d;
}
__device__ __forceinline__ float2 asf2(u64 v) {
    float2 f; asm("mov.b64 {%0, %1}, %2;" : "=f"(f.x), "=f"(f.y) : "l"(v)); return f;
}

__global__ void __launch_bounds__(THREADS, 1)
nn_gather_kernel(const float* __restrict__ pts,
                 const float* __restrict__ lidar,
                 const float* __restrict__ features,
                 float* __restrict__ out)
{
    extern __shared__ float4 sk4[];                 // [N_LIDAR] (x, y, z, ||k||^2)
    __shared__ int sidx[QPB];

    const int tid  = threadIdx.x;
    const int lane = tid & 31;
    const int warp = tid >> 5;

    // Cooperative AoS fill: point + ||k||^2 with stepwise rounding (x^2+y^2)+z^2
    for (int i = tid; i < N_LIDAR; i += THREADS) {
        float kx = lidar[3 * i + 0];
        float ky = lidar[3 * i + 1];
        float kz = lidar[3 * i + 2];
        float ks = __fadd_rn(__fadd_rn(__fmul_rn(kx, kx), __fmul_rn(ky, ky)),
                             __fmul_rn(kz, kz));
        sk4[i] = make_float4(kx, ky, kz, ks);
    }
    __syncthreads();

    const float INF = __int_as_float(0x7f800000);
    const u64 NEG2 = dup2(-2.0f);

    for (int pass = 0; pass < PASSES; pass++) {
        // This warp-pass owns 8 consecutive queries.
        const int ql0 = (pass * WARPS + warp) * QPW;        // block-local query base
        const int mg0 = blockIdx.x * QPB + ql0;             // global query base

        // Load queries (uniform across lanes), exact stepwise ||q||^2,
        // keep ONLY the packed pair forms live through the main loop.
        u64 PQX[QPW / 2], PQY[QPW / 2], PQZ[QPW / 2], PQS[QPW / 2];
        #pragma unroll
        for (int p = 0; p < QPW / 2; p++) {
            float ax = __ldg(pts + 3 * (mg0 + 2 * p) + 0);
            float ay = __ldg(pts + 3 * (mg0 + 2 * p) + 1);
            float az = __ldg(pts + 3 * (mg0 + 2 * p) + 2);
            float bx = __ldg(pts + 3 * (mg0 + 2 * p) + 3);
            float by = __ldg(pts + 3 * (mg0 + 2 * p) + 4);
            float bz = __ldg(pts + 3 * (mg0 + 2 * p) + 5);
            float as = __fadd_rn(__fadd_rn(__fmul_rn(ax, ax), __fmul_rn(ay, ay)),
                                 __fmul_rn(az, az));
            float bs = __fadd_rn(__fadd_rn(__fmul_rn(bx, bx), __fmul_rn(by, by)),
                                 __fmul_rn(bz, bz));
            PQX[p] = pack2(ax, bx);
            PQY[p] = pack2(ay, by);
            PQZ[p] = pack2(az, bz);
            PQS[p] = pack2(as, bs);
        }

        float best[QPW];
        int   btile[QPW];
        #pragma unroll
        for (int q = 0; q < QPW; q++) { best[q] = INF; btile[q] = 0; }

        // Main scan: lane handles points i*32+lane. Tile = TI iters = 256 points.
        for (int t = 0; t < NTILE; t++) {
            float tmin[QPW];
            #pragma unroll
            for (int q = 0; q < QPW; q++) tmin[q] = INF;

            #pragma unroll 2
            for (int ii = 0; ii < TI; ii++) {
                const int i = t * TI + ii;
                const float4 k = sk4[i * 32 + lane];        // coalesced LDS.128
                const u64 KX = dup2(k.x), KY = dup2(k.y);
                const u64 KZ = dup2(k.z), KS = dup2(k.w);

                #pragma unroll
                for (int p = 0; p < QPW / 2; p++) {
                    // cross = fma(qz,kz, fma(qy,ky, rn(qx*kx)))  — reference order
                    u64 cross = fma2(PQZ[p], KZ, fma2(PQY[p], KY, mul2(PQX[p], KX)));
                    // d2 = rn( rn(qs - 2*cross) + ks )
                    u64 d2 = add2(fma2(cross, NEG2, PQS[p]), KS);
                    float2 f = asf2(d2);
                    tmin[2 * p]     = fminf(tmin[2 * p],     f.x);
                    tmin[2 * p + 1] = fminf(tmin[2 * p + 1], f.y);
                }
            }

            #pragma unroll
            for (int q = 0; q < QPW; q++) {
                // strict < : keeps the FIRST tile where this lane's min appeared
                if (tmin[q] < best[q]) { best[q] = tmin[q]; btile[q] = t; }
            }
        }

        // Epilogue: per query -> warp min value, earliest tile, exact first index.
        for (int q = 0; q < QPW; q++) {
            float v = best[q];
            #pragma unroll
            for (int off = 16; off > 0; off >>= 1)
                v = fminf(v, __shfl_xor_sync(0xffffffffu, v, off));

            int tl = (best[q] == v) ? btile[q] : 0x7fffffff;
            #pragma unroll
            for (int off = 16; off > 0; off >>= 1)
                tl = min(tl, __shfl_xor_sync(0xffffffffu, tl, off));

            // Reload this query's scalars (uniform) and rescan winning tile
            // with bit-identical scalar rounding.
            const float fqx = __ldg(pts + 3 * (mg0 + q) + 0);
            const float fqy = __ldg(pts + 3 * (mg0 + q) + 1);
            const float fqz = __ldg(pts + 3 * (mg0 + q) + 2);
            const float fqs = __fadd_rn(__fadd_rn(__fmul_rn(fqx, fqx),
                                                  __fmul_rn(fqy, fqy)),
                                        __fmul_rn(fqz, fqz));
            int cand = 0x7fffffff;
            #pragma unroll
            for (int ii = 0; ii < TI; ii++) {
                const int j = tl * (TI * 32) + ii * 32 + lane;
                const float4 k = sk4[j];
                float cross = __fmaf_rn(fqz, k.z,
                              __fmaf_rn(fqy, k.y, __fmul_rn(fqx, k.x)));
                float d2 = __fadd_rn(__fmaf_rn(cross, -2.0f, fqs), k.w);
                if (d2 == v && j < cand) cand = j;
            }
            #pragma unroll
            for (int off = 16; off > 0; off >>= 1)
                cand = min(cand, __shfl_xor_sync(0xffffffffu, cand, off));

            if (lane == 0) sidx[ql0 + q] = cand;
        }
    }
    __syncthreads();

    // Warp-cooperative coalesced gather: one query row == 32 lanes x float4
    const size_t qbase = (size_t)blockIdx.x * QPB;
    for (int qq = warp; qq < QPB; qq += WARPS) {
        const int src = sidx[qq];
        const float4 v = *(const float4*)(features + (size_t)src * FDIM + lane * 4);
        *(float4*)(out + (qbase + qq) * FDIM + lane * 4) = v;
    }
}

extern "C" void kernel_launch(void* const* d_in, const int* in_sizes, int n_in,
                              void* d_out, int out_size) {
    const float* pts      = (const float*)d_in[0];  // (1, 1024, 32, 3)
    const float* lidar    = (const float*)d_in[1];  // (1, 8192, 3)
    const float* features = (const float*)d_in[2];  // (1, 8192, 128)
    float* out = (float*)d_out;                     // (1, 1024, 32, 128)

    const int smem_bytes = N_LIDAR * (int)sizeof(float4);   // 128 KB AoS
    cudaFuncSetAttribute(nn_gather_kernel,
                         cudaFuncAttributeMaxDynamicSharedMemorySize, smem_bytes);

    nn_gather_kernel<<<NBLK, THREADS, smem_bytes>>>(pts, lidar, features, out);
}

// round 10
// speedup vs baseline: 1.9978x; 1.0753x over previous
#include <cuda_runtime.h>
#include <cstdint>
#include <cstddef>

// Problem constants (fixed by the benchmark shapes)
#define N_QUERY 32768   // 1024 rays * 32 samples
#define N_LIDAR 8192
#define FDIM    128
#define THREADS 512
#define WARPS   (THREADS / 32)      // 16
#define QPW     8                   // queries per warp-pass
#define PASSES  2                   // 16 warps * 2 passes * 8 = 256 queries/block
#define QPB     256
#define NBLK    (N_QUERY / QPB)     // 128 blocks
#define PAIRS   (N_LIDAR / 2)       // 4096 point-pairs
#define NITER   (PAIRS / 32)        // 128 iterations (one pair per lane)
#define TI      4                   // iterations per tile (256 points/tile)
#define NTILE   (NITER / TI)        // 32 tiles

using u64 = unsigned long long;

// ---- packed f32x2 helpers (sm_103a): bitwise-identical per-half to scalar rn ----
__device__ __forceinline__ u64 pack2(float lo, float hi) {
    u64 r; asm("mov.b64 %0, {%1, %2};" : "=l"(r) : "f"(lo), "f"(hi)); return r;
}
__device__ __forceinline__ u64 dup2(float x) {
    u64 r; asm("mov.b64 %0, {%1, %1};" : "=l"(r) : "f"(x)); return r;
}
__device__ __forceinline__ u64 mul2(u64 a, u64 b) {
    u64 d; asm("mul.rn.f32x2 %0, %1, %2;" : "=l"(d) : "l"(a), "l"(b)); return d;
}
__device__ __forceinline__ u64 fma2(u64 a, u64 b, u64 c) {
    u64 d; asm("fma.rn.f32x2 %0, %1, %2, %3;" : "=l"(d) : "l"(a), "l"(b), "l"(c)); return d;
}
__device__ __forceinline__ u64 add2(u64 a, u64 b) {
    u64 d; asm("add.rn.f32x2 %0, %1, %2;" : "=l"(d) : "l"(a), "l"(b)); return d;
}
__device__ __forceinline__ float2 asf2(u64 v) {
    float2 f; asm("mov.b64 {%0, %1}, %2;" : "=f"(f.x), "=f"(f.y) : "l"(v)); return f;
}

__global__ void __launch_bounds__(THREADS, 1)
nn_gather_kernel(const float* __restrict__ pts,
                 const float* __restrict__ lidar,
                 const float* __restrict__ features,
                 float* __restrict__ out)
{
    // Pair-packed lidar: sA[j]=(x0,x1,y0,y1), sB[j]=(z0,z1,s0,s1) for points 2j,2j+1
    extern __shared__ float4 smem4[];
    float4* sA = smem4;                 // [PAIRS]
    float4* sB = smem4 + PAIRS;         // [PAIRS]
    __shared__ int sidx[QPB];

    const int tid  = threadIdx.x;
    const int lane = tid & 31;
    const int warp = tid >> 5;

    // Cooperative pair-packed fill; ||k||^2 with stepwise rounding (x^2+y^2)+z^2
    for (int j = tid; j < PAIRS; j += THREADS) {
        float x0 = lidar[6 * j + 0], y0 = lidar[6 * j + 1], z0 = lidar[6 * j + 2];
        float x1 = lidar[6 * j + 3], y1 = lidar[6 * j + 4], z1 = lidar[6 * j + 5];
        float s0 = __fadd_rn(__fadd_rn(__fmul_rn(x0, x0), __fmul_rn(y0, y0)),
                             __fmul_rn(z0, z0));
        float s1 = __fadd_rn(__fadd_rn(__fmul_rn(x1, x1), __fmul_rn(y1, y1)),
                             __fmul_rn(z1, z1));
        sA[j] = make_float4(x0, x1, y0, y1);
        sB[j] = make_float4(z0, z1, s0, s1);
    }
    __syncthreads();

    const float INF = __int_as_float(0x7f800000);
    const u64 NEG2 = dup2(-2.0f);

    for (int pass = 0; pass < PASSES; pass++) {
        // This warp-pass owns 8 consecutive queries.
        const int ql0 = (pass * WARPS + warp) * QPW;        // block-local query base
        const int mg0 = blockIdx.x * QPB + ql0;             // global query base

        // Duplicated packed query constants (dup2 once per pass — amortized).
        u64 QXd[QPW], QYd[QPW], QZd[QPW], QSd[QPW];
        #pragma unroll
        for (int q = 0; q < QPW; q++) {
            float ax = __ldg(pts + 3 * (mg0 + q) + 0);
            float ay = __ldg(pts + 3 * (mg0 + q) + 1);
            float az = __ldg(pts + 3 * (mg0 + q) + 2);
            float as = __fadd_rn(__fadd_rn(__fmul_rn(ax, ax), __fmul_rn(ay, ay)),
                                 __fmul_rn(az, az));
            QXd[q] = dup2(ax); QYd[q] = dup2(ay);
            QZd[q] = dup2(az); QSd[q] = dup2(as);
        }

        float best[QPW];
        int   btile[QPW];
        #pragma unroll
        for (int q = 0; q < QPW; q++) { best[q] = INF; btile[q] = 0; }

        // Main scan: lane handles pair i*32+lane (points 64i+2*lane, +1).
        // Tile = TI iters = 256 contiguous points.
        for (int t = 0; t < NTILE; t++) {
            float tmin[QPW];
            #pragma unroll
            for (int q = 0; q < QPW; q++) tmin[q] = INF;

            #pragma unroll 2
            for (int ii = 0; ii < TI; ii++) {
                const int i = t * TI + ii;
                const float4 A = sA[i * 32 + lane];   // (x0,x1,y0,y1) — LDS.128
                const float4 B = sB[i * 32 + lane];   // (z0,z1,s0,s1) — LDS.128
                const u64 KX = pack2(A.x, A.y);       // free: aligned reg pair
                const u64 KY = pack2(A.z, A.w);
                const u64 KZ = pack2(B.x, B.y);
                const u64 KS = pack2(B.z, B.w);

                #pragma unroll
                for (int q = 0; q < QPW; q++) {
                    // cross = fma(qz,kz, fma(qy,ky, rn(qx*kx)))  — reference order
                    u64 cross = fma2(QZd[q], KZ, fma2(QYd[q], KY, mul2(QXd[q], KX)));
                    // d2 = rn( rn(qs - 2*cross) + ks )
                    u64 d2 = add2(fma2(cross, NEG2, QSd[q]), KS);
                    float2 f = asf2(d2);              // free unpack
                    tmin[q] = fminf(tmin[q], fminf(f.x, f.y));
                }
            }

            #pragma unroll
            for (int q = 0; q < QPW; q++) {
                // strict < : keeps the FIRST tile where this lane's min appeared
                if (tmin[q] < best[q]) { best[q] = tmin[q]; btile[q] = t; }
            }
        }

        // Epilogue: per query -> warp min value, earliest tile, exact first index.
        for (int q = 0; q < QPW; q++) {
            float v = best[q];
            #pragma unroll
            for (int off = 16; off > 0; off >>= 1)
                v = fminf(v, __shfl_xor_sync(0xffffffffu, v, off));

            int tl = (best[q] == v) ? btile[q] : 0x7fffffff;
            #pragma unroll
            for (int off = 16; off > 0; off >>= 1)
                tl = min(tl, __shfl_xor_sync(0xffffffffu, tl, off));

            // Reload this query's scalars (uniform) and rescan the winning tile
            // with bit-identical scalar rounding.
            const float fqx = __ldg(pts + 3 * (mg0 + q) + 0);
            const float fqy = __ldg(pts + 3 * (mg0 + q) + 1);
            const float fqz = __ldg(pts + 3 * (mg0 + q) + 2);
            const float fqs = __fadd_rn(__fadd_rn(__fmul_rn(fqx, fqx),
                                                  __fmul_rn(fqy, fqy)),
                                        __fmul_rn(fqz, fqz));
            int cand = 0x7fffffff;
            #pragma unroll
            for (int ii = 0; ii < TI; ii++) {
                const int j = (tl * TI + ii) * 32 + lane;   // pair index
                const float4 A = sA[j];
                const float4 B = sB[j];
                float c0 = __fmaf_rn(fqz, B.x,
                           __fmaf_rn(fqy, A.z, __fmul_rn(fqx, A.x)));
                float d0 = __fadd_rn(__fmaf_rn(c0, -2.0f, fqs), B.z);
                if (d0 == v) cand = min(cand, 2 * j);
                float c1 = __fmaf_rn(fqz, B.y,
                           __fmaf_rn(fqy, A.w, __fmul_rn(fqx, A.y)));
                float d1 = __fadd_rn(__fmaf_rn(c1, -2.0f, fqs), B.w);
                if (d1 == v) cand = min(cand, 2 * j + 1);
            }
            #pragma unroll
            for (int off = 16; off > 0; off >>= 1)
                cand = min(cand, __shfl_xor_sync(0xffffffffu, cand, off));

            if (lane == 0) sidx[ql0 + q] = cand;
        }
    }
    __syncthreads();

    // Warp-cooperative coalesced gather: one query row == 32 lanes x float4
    const size_t qbase = (size_t)blockIdx.x * QPB;
    for (int qq = warp; qq < QPB; qq += WARPS) {
        const int src = sidx[qq];
        const float4 v = *(const float4*)(features + (size_t)src * FDIM + lane * 4);
        *(float4*)(out + (qbase + qq) * FDIM + lane * 4) = v;
    }
}

extern "C" void kernel_launch(void* const* d_in, const int* in_sizes, int n_in,
                              void* d_out, int out_size) {
    const float* pts      = (const float*)d_in[0];  // (1, 1024, 32, 3)
    const float* lidar    = (const float*)d_in[1];  // (1, 8192, 3)
    const float* features = (const float*)d_in[2];  // (1, 8192, 128)
    float* out = (float*)d_out;                     // (1, 1024, 32, 128)

    const int smem_bytes = 2 * PAIRS * (int)sizeof(float4);   // 128 KB pair-packed
    cudaFuncSetAttribute(nn_gather_kernel,
                         cudaFuncAttributeMaxDynamicSharedMemorySize, smem_bytes);

    nn_gather_kernel<<<NBLK, THREADS, smem_bytes>>>(pts, lidar, features, out);
}

// round 11
// speedup vs baseline: 2.0969x; 1.0496x over previous
#include <cuda_runtime.h>
#include <cstdint>
#include <cstddef>

// Problem constants (fixed by the benchmark shapes)
#define N_QUERY 32768   // 1024 rays * 32 samples
#define N_LIDAR 8192
#define FDIM    128
#define THREADS 512
#define WARPS   (THREADS / 32)      // 16
#define QPW     8                   // queries per warp-pass
#define PASSES  2                   // 16 warps * 2 passes * 8 = 256 queries/block
#define QPB     256
#define NBLK    (N_QUERY / QPB)     // 128 blocks
#define PAIRS   (N_LIDAR / 2)       // 4096 point-pairs
#define NITER   (PAIRS / 32)        // 128 iterations (one pair per lane)
#define TI      4                   // iterations per tile (256 points/tile)
#define NTILE   (NITER / TI)        // 32 tiles

using u64 = unsigned long long;

// ---- packed f32x2 helpers (sm_103a): bitwise-identical per-half to scalar rn ----
__device__ __forceinline__ u64 pack2(float lo, float hi) {
    u64 r; asm("mov.b64 %0, {%1, %2};" : "=l"(r) : "f"(lo), "f"(hi)); return r;
}
__device__ __forceinline__ u64 dup2(float x) {
    u64 r; asm("mov.b64 %0, {%1, %1};" : "=l"(r) : "f"(x)); return r;
}
__device__ __forceinline__ u64 mul2(u64 a, u64 b) {
    u64 d; asm("mul.rn.f32x2 %0, %1, %2;" : "=l"(d) : "l"(a), "l"(b)); return d;
}
__device__ __forceinline__ u64 fma2(u64 a, u64 b, u64 c) {
    u64 d; asm("fma.rn.f32x2 %0, %1, %2, %3;" : "=l"(d) : "l"(a), "l"(b), "l"(c)); return d;
}
__device__ __forceinline__ u64 add2(u64 a, u64 b) {
    u64 d; asm("add.rn.f32x2 %0, %1, %2;" : "=l"(d) : "l"(a), "l"(b)); return d;
}
__device__ __forceinline__ float2 asf2(u64 v) {
    float2 f; asm("mov.b64 {%0, %1}, %2;" : "=f"(f.x), "=f"(f.y) : "l"(v)); return f;
}

__global__ void __launch_bounds__(THREADS, 1)
nn_gather_kernel(const float* __restrict__ pts,
                 const float* __restrict__ lidar,
                 const float* __restrict__ features,
                 float* __restrict__ out)
{
    // Pair-packed lidar: sA[j]=(x0,x1,y0,y1), sB[j]=(z0,z1,s0,s1) for points 2j,2j+1
    extern __shared__ float4 smem4[];
    float4* sA = smem4;                 // [PAIRS]
    float4* sB = smem4 + PAIRS;         // [PAIRS]
    __shared__ int sidx[QPB];

    const int tid  = threadIdx.x;
    const int lane = tid & 31;
    const int warp = tid >> 5;

    // Cooperative pair-packed fill; ||k||^2 with stepwise rounding (x^2+y^2)+z^2
    for (int j = tid; j < PAIRS; j += THREADS) {
        float x0 = lidar[6 * j + 0], y0 = lidar[6 * j + 1], z0 = lidar[6 * j + 2];
        float x1 = lidar[6 * j + 3], y1 = lidar[6 * j + 4], z1 = lidar[6 * j + 5];
        float s0 = __fadd_rn(__fadd_rn(__fmul_rn(x0, x0), __fmul_rn(y0, y0)),
                             __fmul_rn(z0, z0));
        float s1 = __fadd_rn(__fadd_rn(__fmul_rn(x1, x1), __fmul_rn(y1, y1)),
                             __fmul_rn(z1, z1));
        sA[j] = make_float4(x0, x1, y0, y1);
        sB[j] = make_float4(z0, z1, s0, s1);
    }
    __syncthreads();

    const float INF = __int_as_float(0x7f800000);
    const u64 NEG2 = dup2(-2.0f);

    for (int pass = 0; pass < PASSES; pass++) {
        // This warp-pass owns 8 consecutive queries.
        const int ql0 = (pass * WARPS + warp) * QPW;        // block-local query base
        const int mg0 = blockIdx.x * QPB + ql0;             // global query base

        // Duplicated packed query constants (dup2 once per pass — amortized).
        u64 QXd[QPW], QYd[QPW], QZd[QPW], QSd[QPW];
        #pragma unroll
        for (int q = 0; q < QPW; q++) {
            float ax = __ldg(pts + 3 * (mg0 + q) + 0);
            float ay = __ldg(pts + 3 * (mg0 + q) + 1);
            float az = __ldg(pts + 3 * (mg0 + q) + 2);
            float as = __fadd_rn(__fadd_rn(__fmul_rn(ax, ax), __fmul_rn(ay, ay)),
                                 __fmul_rn(az, az));
            QXd[q] = dup2(ax); QYd[q] = dup2(ay);
            QZd[q] = dup2(az); QSd[q] = dup2(as);
        }

        float best[QPW];
        int   btile[QPW];
        float tmin[QPW];
        #pragma unroll
        for (int q = 0; q < QPW; q++) { best[q] = INF; btile[q] = 0; tmin[q] = INF; }

        // Software-pipelined scan: prefetch iter i+1's pair while computing iter i.
        // Lane handles pair i*32+lane (points 64i+2*lane, +1); tile = 4 iters.
        float4 A = sA[lane];
        float4 B = sB[lane];

        #pragma unroll 4
        for (int i = 0; i < NITER; i++) {
            // Prefetch next iteration (clamped dummy reload on the last iter).
            const int nx = (i + 1 < NITER) ? (i + 1) : i;
            const float4 An = sA[nx * 32 + lane];
            const float4 Bn = sB[nx * 32 + lane];

            const u64 KX = pack2(A.x, A.y);       // free: aligned reg pairs
            const u64 KY = pack2(A.z, A.w);
            const u64 KZ = pack2(B.x, B.y);
            const u64 KS = pack2(B.z, B.w);

            #pragma unroll
            for (int q = 0; q < QPW; q++) {
                // cross = fma(qz,kz, fma(qy,ky, rn(qx*kx)))  — reference order
                u64 cross = fma2(QZd[q], KZ, fma2(QYd[q], KY, mul2(QXd[q], KX)));
                // d2 = rn( rn(qs - 2*cross) + ks )
                u64 d2 = add2(fma2(cross, NEG2, QSd[q]), KS);
                float2 f = asf2(d2);              // free unpack
                tmin[q] = fminf(tmin[q], fminf(f.x, f.y));
            }

            if ((i & (TI - 1)) == TI - 1) {       // static under unroll 4
                const int t = i >> 2;
                #pragma unroll
                for (int q = 0; q < QPW; q++) {
                    // strict < : keeps the FIRST tile where this lane's min appeared
                    if (tmin[q] < best[q]) { best[q] = tmin[q]; btile[q] = t; }
                    tmin[q] = INF;
                }
            }

            A = An; B = Bn;
        }

        // Epilogue: per query -> warp min value, earliest tile, exact first index.
        for (int q = 0; q < QPW; q++) {
            float v = best[q];
            #pragma unroll
            for (int off = 16; off > 0; off >>= 1)
                v = fminf(v, __shfl_xor_sync(0xffffffffu, v, off));

            int tl = (best[q] == v) ? btile[q] : 0x7fffffff;
            #pragma unroll
            for (int off = 16; off > 0; off >>= 1)
                tl = min(tl, __shfl_xor_sync(0xffffffffu, tl, off));

            // Reload this query's scalars (uniform) and rescan the winning tile
            // with bit-identical scalar rounding.
            const float fqx = __ldg(pts + 3 * (mg0 + q) + 0);
            const float fqy = __ldg(pts + 3 * (mg0 + q) + 1);
            const float fqz = __ldg(pts + 3 * (mg0 + q) + 2);
            const float fqs = __fadd_rn(__fadd_rn(__fmul_rn(fqx, fqx),
                                                  __fmul_rn(fqy, fqy)),
                                        __fmul_rn(fqz, fqz));
            int cand = 0x7fffffff;
            #pragma unroll
            for (int ii = 0; ii < TI; ii++) {
                const int j = (tl * TI + ii) * 32 + lane;   // pair index
                const float4 Ar = sA[j];
                const float4 Br = sB[j];
                float c0 = __fmaf_rn(fqz, Br.x,
                           __fmaf_rn(fqy, Ar.z, __fmul_rn(fqx, Ar.x)));
                float d0 = __fadd_rn(__fmaf_rn(c0, -2.0f, fqs), Br.z);
                if (d0 == v) cand = min(cand, 2 * j);
                float c1 = __fmaf_rn(fqz, Br.y,
                           __fmaf_rn(fqy, Ar.w, __fmul_rn(fqx, Ar.y)));
                float d1 = __fadd_rn(__fmaf_rn(c1, -2.0f, fqs), Br.w);
                if (d1 == v) cand = min(cand, 2 * j + 1);
            }
            #pragma unroll
            for (int off = 16; off > 0; off >>= 1)
                cand = min(cand, __shfl_xor_sync(0xffffffffu, cand, off));

            if (lane == 0) sidx[ql0 + q] = cand;
        }
    }
    __syncthreads();

    // Warp-cooperative coalesced gather: one query row == 32 lanes x float4
    const size_t qbase = (size_t)blockIdx.x * QPB;
    for (int qq = warp; qq < QPB; qq += WARPS) {
        const int src = sidx[qq];
        const float4 v = *(const float4*)(features + (size_t)src * FDIM + lane * 4);
        *(float4*)(out + (qbase + qq) * FDIM + lane * 4) = v;
    }
}

extern "C" void kernel_launch(void* const* d_in, const int* in_sizes, int n_in,
                              void* d_out, int out_size) {
    const float* pts      = (const float*)d_in[0];  // (1, 1024, 32, 3)
    const float* lidar    = (const float*)d_in[1];  // (1, 8192, 3)
    const float* features = (const float*)d_in[2];  // (1, 8192, 128)
    float* out = (float*)d_out;                     // (1, 1024, 32, 128)

    const int smem_bytes = 2 * PAIRS * (int)sizeof(float4);   // 128 KB pair-packed
    cudaFuncSetAttribute(nn_gather_kernel,
                         cudaFuncAttributeMaxDynamicSharedMemorySize, smem_bytes);

    nn_gather_kernel<<<NBLK, THREADS, smem_bytes>>>(pts, lidar, features, out);
}

// round 12
// speedup vs baseline: 2.3062x; 1.0998x over previous
#include <cuda_runtime.h>
#include <cstdint>
#include <cstddef>

// Problem constants (fixed by the benchmark shapes)
#define N_QUERY 32768   // 1024 rays * 32 samples
#define N_LIDAR 8192
#define FDIM    128
#define THREADS 512
#define WARPS   (THREADS / 32)      // 16
#define QPW     7                   // queries per warp-pass
#define PASSES  2                   // 16 warps * 2 passes * 7 = 224 queries/block
#define QPB     (WARPS * QPW * PASSES)          // 224
#define NBLK    ((N_QUERY + QPB - 1) / QPB)     // 147 blocks -> one full wave
#define PAIRS   (N_LIDAR / 2)       // 4096 point-pairs
#define NITER   (PAIRS / 32)        // 128 iterations (one pair per lane)
#define TI      4                   // iterations per tile (256 points/tile)
#define NTILE   (NITER / TI)        // 32 tiles

using u64 = unsigned long long;

// ---- packed f32x2 helpers (sm_103a): bitwise-identical per-half to scalar rn ----
__device__ __forceinline__ u64 pack2(float lo, float hi) {
    u64 r; asm("mov.b64 %0, {%1, %2};" : "=l"(r) : "f"(lo), "f"(hi)); return r;
}
__device__ __forceinline__ u64 dup2(float x) {
    u64 r; asm("mov.b64 %0, {%1, %1};" : "=l"(r) : "f"(x)); return r;
}
__device__ __forceinline__ u64 mul2(u64 a, u64 b) {
    u64 d; asm("mul.rn.f32x2 %0, %1, %2;" : "=l"(d) : "l"(a), "l"(b)); return d;
}
__device__ __forceinline__ u64 fma2(u64 a, u64 b, u64 c) {
    u64 d; asm("fma.rn.f32x2 %0, %1, %2, %3;" : "=l"(d) : "l"(a), "l"(b), "l"(c)); return d;
}
__device__ __forceinline__ u64 add2(u64 a, u64 b) {
    u64 d; asm("add.rn.f32x2 %0, %1, %2;" : "=l"(d) : "l"(a), "l"(b)); return d;
}
__device__ __forceinline__ float2 asf2(u64 v) {
    float2 f; asm("mov.b64 {%0, %1}, %2;" : "=f"(f.x), "=f"(f.y) : "l"(v)); return f;
}

__global__ void __launch_bounds__(THREADS, 1)
nn_gather_kernel(const float* __restrict__ pts,
                 const float* __restrict__ lidar,
                 const float* __restrict__ features,
                 float* __restrict__ out)
{
    // Pair-packed lidar: sA[j]=(x0,x1,y0,y1), sB[j]=(z0,z1,s0,s1) for points 2j,2j+1
    extern __shared__ float4 smem4[];
    float4* sA = smem4;                 // [PAIRS]
    float4* sB = smem4 + PAIRS;         // [PAIRS]
    __shared__ int sidx[QPB];

    const int tid  = threadIdx.x;
    const int lane = tid & 31;
    const int warp = tid >> 5;

    // Cooperative pair-packed fill; ||k||^2 with stepwise rounding (x^2+y^2)+z^2
    for (int j = tid; j < PAIRS; j += THREADS) {
        float x0 = lidar[6 * j + 0], y0 = lidar[6 * j + 1], z0 = lidar[6 * j + 2];
        float x1 = lidar[6 * j + 3], y1 = lidar[6 * j + 4], z1 = lidar[6 * j + 5];
        float s0 = __fadd_rn(__fadd_rn(__fmul_rn(x0, x0), __fmul_rn(y0, y0)),
                             __fmul_rn(z0, z0));
        float s1 = __fadd_rn(__fadd_rn(__fmul_rn(x1, x1), __fmul_rn(y1, y1)),
                             __fmul_rn(z1, z1));
        sA[j] = make_float4(x0, x1, y0, y1);
        sB[j] = make_float4(z0, z1, s0, s1);
    }
    __syncthreads();

    const float INF = __int_as_float(0x7f800000);
    const u64 NEG2 = dup2(-2.0f);
    const int qbase = blockIdx.x * QPB;             // global query base of block

    for (int pass = 0; pass < PASSES; pass++) {
        // This warp-pass owns QPW consecutive queries.
        const int ql0 = (pass * WARPS + warp) * QPW;    // block-local query base
        const int mg0 = qbase + ql0;                    // global query base

        // Duplicated packed query constants (dup2 once per pass — amortized).
        // Tail safety: clamp the load index; results for m >= N_QUERY discarded.
        u64 QXd[QPW], QYd[QPW], QZd[QPW], QSd[QPW];
        #pragma unroll
        for (int q = 0; q < QPW; q++) {
            const int m = min(mg0 + q, N_QUERY - 1);
            float ax = __ldg(pts + 3 * m + 0);
            float ay = __ldg(pts + 3 * m + 1);
            float az = __ldg(pts + 3 * m + 2);
            float as = __fadd_rn(__fadd_rn(__fmul_rn(ax, ax), __fmul_rn(ay, ay)),
                                 __fmul_rn(az, az));
            QXd[q] = dup2(ax); QYd[q] = dup2(ay);
            QZd[q] = dup2(az); QSd[q] = dup2(as);
        }

        float best[QPW];
        int   btile[QPW];
        float tmin[QPW];
        #pragma unroll
        for (int q = 0; q < QPW; q++) { best[q] = INF; btile[q] = 0; tmin[q] = INF; }

        // Software-pipelined scan: prefetch iter i+1's pair while computing iter i.
        // Lane handles pair i*32+lane (points 64i+2*lane, +1); tile = 4 iters.
        float4 A = sA[lane];
        float4 B = sB[lane];

        #pragma unroll 4
        for (int i = 0; i < NITER; i++) {
            // Prefetch next iteration (clamped dummy reload on the last iter).
            const int nx = (i + 1 < NITER) ? (i + 1) : i;
            const float4 An = sA[nx * 32 + lane];
            const float4 Bn = sB[nx * 32 + lane];

            const u64 KX = pack2(A.x, A.y);       // free: aligned reg pairs
            const u64 KY = pack2(A.z, A.w);
            const u64 KZ = pack2(B.x, B.y);
            const u64 KS = pack2(B.z, B.w);

            #pragma unroll
            for (int q = 0; q < QPW; q++) {
                // cross = fma(qz,kz, fma(qy,ky, rn(qx*kx)))  — reference order
                u64 cross = fma2(QZd[q], KZ, fma2(QYd[q], KY, mul2(QXd[q], KX)));
                // d2 = rn( rn(qs - 2*cross) + ks )
                u64 d2 = add2(fma2(cross, NEG2, QSd[q]), KS);
                float2 f = asf2(d2);              // free unpack
                tmin[q] = fminf(tmin[q], fminf(f.x, f.y));
            }

            if ((i & (TI - 1)) == TI - 1) {       // static under unroll 4
                const int t = i >> 2;
                #pragma unroll
                for (int q = 0; q < QPW; q++) {
                    // strict < : keeps the FIRST tile where this lane's min appeared
                    if (tmin[q] < best[q]) { best[q] = tmin[q]; btile[q] = t; }
                    tmin[q] = INF;
                }
            }

            A = An; B = Bn;
        }

        // Epilogue: per query -> warp min value, earliest tile, exact first index.
        for (int q = 0; q < QPW; q++) {
            float v = best[q];
            #pragma unroll
            for (int off = 16; off > 0; off >>= 1)
                v = fminf(v, __shfl_xor_sync(0xffffffffu, v, off));

            int tl = (best[q] == v) ? btile[q] : 0x7fffffff;
            #pragma unroll
            for (int off = 16; off > 0; off >>= 1)
                tl = min(tl, __shfl_xor_sync(0xffffffffu, tl, off));

            // Reload this query's scalars (uniform) and rescan the winning tile
            // with bit-identical scalar rounding.
            const int m = min(mg0 + q, N_QUERY - 1);
            const float fqx = __ldg(pts + 3 * m + 0);
            const float fqy = __ldg(pts + 3 * m + 1);
            const float fqz = __ldg(pts + 3 * m + 2);
            const float fqs = __fadd_rn(__fadd_rn(__fmul_rn(fqx, fqx),
                                                  __fmul_rn(fqy, fqy)),
                                        __fmul_rn(fqz, fqz));
            int cand = 0x7fffffff;
            #pragma unroll
            for (int ii = 0; ii < TI; ii++) {
                const int j = (tl * TI + ii) * 32 + lane;   // pair index
                const float4 Ar = sA[j];
                const float4 Br = sB[j];
                float c0 = __fmaf_rn(fqz, Br.x,
                           __fmaf_rn(fqy, Ar.z, __fmul_rn(fqx, Ar.x)));
                float d0 = __fadd_rn(__fmaf_rn(c0, -2.0f, fqs), Br.z);
                if (d0 == v) cand = min(cand, 2 * j);
                float c1 = __fmaf_rn(fqz, Br.y,
                           __fmaf_rn(fqy, Ar.w, __fmul_rn(fqx, Ar.y)));
                float d1 = __fadd_rn(__fmaf_rn(c1, -2.0f, fqs), Br.w);
                if (d1 == v) cand = min(cand, 2 * j + 1);
            }
            #pragma unroll
            for (int off = 16; off > 0; off >>= 1)
                cand = min(cand, __shfl_xor_sync(0xffffffffu, cand, off));

            if (lane == 0 && (mg0 + q) < N_QUERY) sidx[ql0 + q] = cand;
        }
    }
    __syncthreads();

    // Warp-cooperative coalesced gather: one query row == 32 lanes x float4
    for (int qq = warp; qq < QPB; qq += WARPS) {
        const int m = qbase + qq;
        if (m >= N_QUERY) break;
        const int src = sidx[qq];
        const float4 v = *(const float4*)(features + (size_t)src * FDIM + lane * 4);
        *(float4*)(out + (size_t)m * FDIM + lane * 4) = v;
    }
}

extern "C" void kernel_launch(void* const* d_in, const int* in_sizes, int n_in,
                              void* d_out, int out_size) {
    const float* pts      = (const float*)d_in[0];  // (1, 1024, 32, 3)
    const float* lidar    = (const float*)d_in[1];  // (1, 8192, 3)
    const float* features = (const float*)d_in[2];  // (1, 8192, 128)
    float* out = (float*)d_out;                     // (1, 1024, 32, 128)

    const int smem_bytes = 2 * PAIRS * (int)sizeof(float4);   // 128 KB pair-packed
    cudaFuncSetAttribute(nn_gather_kernel,
                         cudaFuncAttributeMaxDynamicSharedMemorySize, smem_bytes);

    nn_gather_kernel<<<NBLK, THREADS, smem_bytes>>>(pts, lidar, features, out);
}

// round 13
// speedup vs baseline: 2.3158x; 1.0041x over previous
#include <cuda_runtime.h>
#include <cstdint>
#include <cstddef>

// Problem constants (fixed by the benchmark shapes)
#define N_QUERY 32768   // 1024 rays * 32 samples
#define N_LIDAR 8192
#define FDIM    128
#define THREADS 512
#define WARPS   (THREADS / 32)      // 16
#define QPW     7                   // queries per warp-pass
#define PASSES  2                   // 16 warps * 2 passes * 7 = 224 queries/block
#define QPB     (WARPS * QPW * PASSES)          // 224
#define NBLK    ((N_QUERY + QPB - 1) / QPB)     // 147 blocks -> one full wave
#define PAIRS   (N_LIDAR / 2)       // 4096 point-pairs
#define NITER   (PAIRS / 32)        // 128 iterations (one pair per lane)
#define TI      4                   // iterations per tile (256 points/tile)
#define NTILE   (NITER / TI)        // 32 tiles

using u64 = unsigned long long;

// ---- packed f32x2 helpers (sm_103a): bitwise-identical per-half to scalar rn ----
__device__ __forceinline__ u64 pack2(float lo, float hi) {
    u64 r; asm("mov.b64 %0, {%1, %2};" : "=l"(r) : "f"(lo), "f"(hi)); return r;
}
__device__ __forceinline__ u64 dup2(float x) {
    u64 r; asm("mov.b64 %0, {%1, %1};" : "=l"(r) : "f"(x)); return r;
}
__device__ __forceinline__ u64 mul2(u64 a, u64 b) {
    u64 d; asm("mul.rn.f32x2 %0, %1, %2;" : "=l"(d) : "l"(a), "l"(b)); return d;
}
__device__ __forceinline__ u64 fma2(u64 a, u64 b, u64 c) {
    u64 d; asm("fma.rn.f32x2 %0, %1, %2, %3;" : "=l"(d) : "l"(a), "l"(b), "l"(c)); return d;
}
__device__ __forceinline__ u64 add2(u64 a, u64 b) {
    u64 d; asm("add.rn.f32x2 %0, %1, %2;" : "=l"(d) : "l"(a), "l"(b)); return d;
}
__device__ __forceinline__ float2 asf2(u64 v) {
    float2 f; asm("mov.b64 {%0, %1}, %2;" : "=f"(f.x), "=f"(f.y) : "l"(v)); return f;
}

__global__ void __launch_bounds__(THREADS, 1)
nn_gather_kernel(const float* __restrict__ pts,
                 const float* __restrict__ lidar,
                 const float* __restrict__ features,
                 float* __restrict__ out)
{
    // Pair-packed, PRE-SCALED lidar: for points 2j, 2j+1
    //   sA[j] = (-2*x0, -2*x1, -2*y0, -2*y1)
    //   sB[j] = (-2*z0, -2*z1,  s0,    s1 )   (s = ||k||^2, unscaled)
    // Scaling by -2 is exact; rn(-2u) = -2*rn(u), so the dot chain below produces
    // exactly -2*cross with the reference's rounding at every step.
    extern __shared__ float4 smem4[];
    float4* sA = smem4;                 // [PAIRS]
    float4* sB = smem4 + PAIRS;         // [PAIRS]
    __shared__ int sidx[QPB];

    const int tid  = threadIdx.x;
    const int lane = tid & 31;
    const int warp = tid >> 5;

    // Cooperative fill; ||k||^2 with stepwise rounding (x^2+y^2)+z^2 on UNSCALED values
    for (int j = tid; j < PAIRS; j += THREADS) {
        float x0 = lidar[6 * j + 0], y0 = lidar[6 * j + 1], z0 = lidar[6 * j + 2];
        float x1 = lidar[6 * j + 3], y1 = lidar[6 * j + 4], z1 = lidar[6 * j + 5];
        float s0 = __fadd_rn(__fadd_rn(__fmul_rn(x0, x0), __fmul_rn(y0, y0)),
                             __fmul_rn(z0, z0));
        float s1 = __fadd_rn(__fadd_rn(__fmul_rn(x1, x1), __fmul_rn(y1, y1)),
                             __fmul_rn(z1, z1));
        sA[j] = make_float4(-2.0f * x0, -2.0f * x1, -2.0f * y0, -2.0f * y1);
        sB[j] = make_float4(-2.0f * z0, -2.0f * z1, s0, s1);
    }
    __syncthreads();

    const float INF = __int_as_float(0x7f800000);
    const int qbase = blockIdx.x * QPB;             // global query base of block

    for (int pass = 0; pass < PASSES; pass++) {
        // This warp-pass owns QPW consecutive queries.
        const int ql0 = (pass * WARPS + warp) * QPW;    // block-local query base
        const int mg0 = qbase + ql0;                    // global query base

        // Duplicated packed query constants (dup2 once per pass — amortized).
        // Tail safety: clamp the load index; results for m >= N_QUERY discarded.
        u64 QXd[QPW], QYd[QPW], QZd[QPW], QSd[QPW];
        #pragma unroll
        for (int q = 0; q < QPW; q++) {
            const int m = min(mg0 + q, N_QUERY - 1);
            float ax = __ldg(pts + 3 * m + 0);
            float ay = __ldg(pts + 3 * m + 1);
            float az = __ldg(pts + 3 * m + 2);
            float as = __fadd_rn(__fadd_rn(__fmul_rn(ax, ax), __fmul_rn(ay, ay)),
                                 __fmul_rn(az, az));
            QXd[q] = dup2(ax); QYd[q] = dup2(ay);
            QZd[q] = dup2(az); QSd[q] = dup2(as);
        }

        float best[QPW];
        int   btile[QPW];
        float tmin[QPW];
        #pragma unroll
        for (int q = 0; q < QPW; q++) { best[q] = INF; btile[q] = 0; tmin[q] = INF; }

        // Software-pipelined scan: prefetch iter i+1's pair while computing iter i.
        // Lane handles pair i*32+lane (points 64i+2*lane, +1); tile = 4 iters.
        float4 A = sA[lane];
        float4 B = sB[lane];

        #pragma unroll 4
        for (int i = 0; i < NITER; i++) {
            // Prefetch next iteration (clamped dummy reload on the last iter).
            const int nx = (i + 1 < NITER) ? (i + 1) : i;
            const float4 An = sA[nx * 32 + lane];
            const float4 Bn = sB[nx * 32 + lane];

            const u64 KX = pack2(A.x, A.y);       // (-2x0, -2x1) — free reg pair
            const u64 KY = pack2(A.z, A.w);       // (-2y0, -2y1)
            const u64 KZ = pack2(B.x, B.y);       // (-2z0, -2z1)
            const u64 KS = pack2(B.z, B.w);       // ( s0,   s1 )

            #pragma unroll
            for (int q = 0; q < QPW; q++) {
                // c' = fma(qz,-2kz, fma(qy,-2ky, rn(qx*-2kx))) == -2*cross, exact
                u64 c = fma2(QZd[q], KZ, fma2(QYd[q], KY, mul2(QXd[q], KX)));
                // d2 = rn( rn(qs + c') + ks )  == rn( rn(qs - 2*cross) + ks )
                u64 d2 = add2(add2(QSd[q], c), KS);
                float2 f = asf2(d2);              // free unpack
                tmin[q] = fminf(tmin[q], fminf(f.x, f.y));
            }

            if ((i & (TI - 1)) == TI - 1) {       // static under unroll 4
                const int t = i >> 2;
                #pragma unroll
                for (int q = 0; q < QPW; q++) {
                    // strict < : keeps the FIRST tile where this lane's min appeared
                    if (tmin[q] < best[q]) { best[q] = tmin[q]; btile[q] = t; }
                    tmin[q] = INF;
                }
            }

            A = An; B = Bn;
        }

        // Epilogue: per query -> warp min value, earliest tile, exact first index.
        for (int q = 0; q < QPW; q++) {
            float v = best[q];
            #pragma unroll
            for (int off = 16; off > 0; off >>= 1)
                v = fminf(v, __shfl_xor_sync(0xffffffffu, v, off));

            int tl = (best[q] == v) ? btile[q] : 0x7fffffff;
            #pragma unroll
            for (int off = 16; off > 0; off >>= 1)
                tl = min(tl, __shfl_xor_sync(0xffffffffu, tl, off));

            // Reload this query's scalars (uniform) and rescan the winning tile
            // with the same bit-exact sequence on the scaled inputs.
            const int m = min(mg0 + q, N_QUERY - 1);
            const float fqx = __ldg(pts + 3 * m + 0);
            const float fqy = __ldg(pts + 3 * m + 1);
            const float fqz = __ldg(pts + 3 * m + 2);
            const float fqs = __fadd_rn(__fadd_rn(__fmul_rn(fqx, fqx),
                                                  __fmul_rn(fqy, fqy)),
                                        __fmul_rn(fqz, fqz));
            int cand = 0x7fffffff;
            #pragma unroll
            for (int ii = 0; ii < TI; ii++) {
                const int j = (tl * TI + ii) * 32 + lane;   // pair index
                const float4 Ar = sA[j];
                const float4 Br = sB[j];
                float c0 = __fmaf_rn(fqz, Br.x,
                           __fmaf_rn(fqy, Ar.z, __fmul_rn(fqx, Ar.x)));
                float d0 = __fadd_rn(__fadd_rn(fqs, c0), Br.z);
                if (d0 == v) cand = min(cand, 2 * j);
                float c1 = __fmaf_rn(fqz, Br.y,
                           __fmaf_rn(fqy, Ar.w, __fmul_rn(fqx, Ar.y)));
                float d1 = __fadd_rn(__fadd_rn(fqs, c1), Br.w);
                if (d1 == v) cand = min(cand, 2 * j + 1);
            }
            #pragma unroll
            for (int off = 16; off > 0; off >>= 1)
                cand = min(cand, __shfl_xor_sync(0xffffffffu, cand, off));

            if (lane == 0 && (mg0 + q) < N_QUERY) sidx[ql0 + q] = cand;
        }
    }
    __syncthreads();

    // Warp-cooperative coalesced gather: one query row == 32 lanes x float4
    for (int qq = warp; qq < QPB; qq += WARPS) {
        const int m = qbase + qq;
        if (m >= N_QUERY) break;
        const int src = sidx[qq];
        const float4 v = *(const float4*)(features + (size_t)src * FDIM + lane * 4);
        *(float4*)(out + (size_t)m * FDIM + lane * 4) = v;
    }
}

extern "C" void kernel_launch(void* const* d_in, const int* in_sizes, int n_in,
                              void* d_out, int out_size) {
    const float* pts      = (const float*)d_in[0];  // (1, 1024, 32, 3)
    const float* lidar    = (const float*)d_in[1];  // (1, 8192, 3)
    const float* features = (const float*)d_in[2];  // (1, 8192, 128)
    float* out = (float*)d_out;                     // (1, 1024, 32, 128)

    const int smem_bytes = 2 * PAIRS * (int)sizeof(float4);   // 128 KB pair-packed
    cudaFuncSetAttribute(nn_gather_kernel,
                         cudaFuncAttributeMaxDynamicSharedMemorySize, smem_bytes);

    nn_gather_kernel<<<NBLK, THREADS, smem_bytes>>>(pts, lidar, features, out);
}